// round 16
// baseline (speedup 1.0000x reference)
#include <cuda_runtime.h>
#include <cuda_fp16.h>

#define NSEQ 1024
#define CH   64
#define NPTS (2 * NSEQ)

// Scratch (allocation-free rule: __device__ globals). fp16 projections.
__device__ __align__(16) __half g_Hi[NPTS * CH];  //  y + b1   (i side)
__device__ __align__(16) __half g_Hj[NPTS * CH];  // -y        (j side, pre-negated)
__device__ float g_rowsum[NPTS];                  // per-(b,i) sum of exp(s)
__device__ unsigned g_cnt[32];                    // per-(b,it) tickets (monotonic)
__device__ unsigned g_sync;                       // grid barrier ticket (monotonic)

static __device__ __forceinline__ __half2 u2h(unsigned u) {
    return *reinterpret_cast<const __half2*>(&u);
}
static __device__ __forceinline__ unsigned h2u(__half2 h) {
    return *reinterpret_cast<const unsigned*>(&h);
}

// ---------------------------------------------------------------------------
// Fused kernel: projection (phase 0) + grid barrier + scores/softmax (phase 1).
// Grid (jt=8, it=16, b=2) = 256 blocks, 512 threads, 2 CTAs/SM (co-resident).
// Phase-0 and phase-1 smem are time-disjoint (separated by the grid barrier)
// and share one union (static smem ~35KB < 48KB limit).
// ---------------------------------------------------------------------------
__global__ void __launch_bounds__(512, 2)
k_fused(const float* __restrict__ x,
        const float* __restrict__ w1,
        const float* __restrict__ b1,
        const float* __restrict__ w2,
        const float* __restrict__ b2p,
        float* __restrict__ out) {
    __shared__ __align__(16) union {
        struct {
            float W1T[CH][65];   // [c][o]
            float xsT[CH][12];   // [c][p] (8 points + pad)
            float b1s[CH];
        } p0;
        struct {
            unsigned His[64][66];  // dup'd (yi,yi)
            unsigned Hjs[64][66];  // paired (yj0,yj1)
        } p1;
    } S;
    __shared__ __align__(16) unsigned wdup[CH];      // dup'd (w2h,w2h)
    __shared__ float w2hs[CH];
    __shared__ float rIs[64], rJn[128];
    __shared__ float rsum[64];

    int t  = threadIdx.x;
    int jt = blockIdx.x, it = blockIdx.y, b = blockIdx.z;
    int bid = (b * 16 + it) * 8 + jt;              // 0..255

    // ======================= PHASE 0: projection ==========================
    if (t < 8) g_rowsum[bid * 8 + t] = 0.f;

    // stage W1 transposed [c][o]: 1024 float4, 2 per thread
#pragma unroll
    for (int q = t; q < 1024; q += 512) {
        int o = q >> 4, c4 = (q & 15) * 4;
        float4 v = reinterpret_cast<const float4*>(w1)[q];
        S.p0.W1T[c4 + 0][o] = v.x;
        S.p0.W1T[c4 + 1][o] = v.y;
        S.p0.W1T[c4 + 2][o] = v.z;
        S.p0.W1T[c4 + 3][o] = v.w;
    }
    int p0 = bid * 8;   // 8 points per block
    if (t < 128) {      // 8 points x 64 ch = 128 float4
        int pl = t >> 4, c4 = (t & 15) * 4;
        float4 v = reinterpret_cast<const float4*>(x + p0 * CH)[t];
        S.p0.xsT[c4 + 0][pl] = v.x;
        S.p0.xsT[c4 + 1][pl] = v.y;
        S.p0.xsT[c4 + 2][pl] = v.z;
        S.p0.xsT[c4 + 3][pl] = v.w;
    }
    if (t < CH) S.p0.b1s[t] = b1[t];
    __syncthreads();

    {
        int o = t & 63, pg = t >> 6;   // pg 0..7, one point each
        float acc = 0.f;
#pragma unroll
        for (int c = 0; c < CH; ++c)
            acc += S.p0.W1T[c][o] * S.p0.xsT[c][pg];
        int p = p0 + pg;
        g_Hj[p * CH + o] = __float2half_rn(-acc);
        g_Hi[p * CH + o] = __float2half_rn(acc + S.p0.b1s[o]);
    }

    // ======================= grid-wide barrier ============================
    __threadfence();
    __syncthreads();
    if (t == 0) {
        unsigned ticket = atomicAdd(&g_sync, 1u);
        unsigned target = (ticket / 256u + 1u) * 256u;
        while (atomicAdd(&g_sync, 0u) < target) { __nanosleep(32); }
    }
    __syncthreads();
    __threadfence();

    // ======================= PHASE 1: scores + softmax ====================
    size_t bb = (size_t)b * NSEQ * CH;

    // stage His (dup): thread -> row t>>3, 8 channels
    {
        int row = t >> 3, c8 = (t & 7) * 8;
        uint4 u = *reinterpret_cast<const uint4*>(
            g_Hi + bb + (size_t)(it * 64 + row) * CH + c8);
        unsigned wsrc[4] = {u.x, u.y, u.z, u.w};
#pragma unroll
        for (int k = 0; k < 4; ++k) {
            S.p1.His[row][c8 + 2 * k]     = __byte_perm(wsrc[k], 0, 0x1010);
            S.p1.His[row][c8 + 2 * k + 1] = __byte_perm(wsrc[k], 0, 0x3232);
        }
    }
    // stage Hjs (j-pairs): thread -> jp = t>>3, 8 channels
    {
        int jp = t >> 3, c8 = (t & 7) * 8;
        uint4 A = *reinterpret_cast<const uint4*>(
            g_Hj + bb + (size_t)(jt * 128 + 2 * jp) * CH + c8);
        uint4 B = *reinterpret_cast<const uint4*>(
            g_Hj + bb + (size_t)(jt * 128 + 2 * jp + 1) * CH + c8);
        unsigned av[4] = {A.x, A.y, A.z, A.w};
        unsigned bv[4] = {B.x, B.y, B.z, B.w};
#pragma unroll
        for (int k = 0; k < 4; ++k) {
            S.p1.Hjs[jp][c8 + 2 * k]     = __byte_perm(av[k], bv[k], 0x5410);
            S.p1.Hjs[jp][c8 + 2 * k + 1] = __byte_perm(av[k], bv[k], 0x7632);
        }
    }
    if (t < CH) {
        float wh = 0.5f * w2[t];
        w2hs[t] = wh;
        wdup[t] = h2u(__half2half2(__float2half_rn(wh)));
    }
    __syncthreads();

    // per-row scalars (fp32, ILP-4), overlapped with the main loop
    if (t < 64) {
        const __half2* row = reinterpret_cast<const __half2*>(&S.p1.His[t][0]);
        float a0 = 0.f, a1 = 0.f, a2 = 0.f, a3 = 0.f;
#pragma unroll
        for (int c = 0; c < CH; c += 4) {
            a0 += w2hs[c + 0] * __low2float(row[c + 0]);
            a1 += w2hs[c + 1] * __low2float(row[c + 1]);
            a2 += w2hs[c + 2] * __low2float(row[c + 2]);
            a3 += w2hs[c + 3] * __low2float(row[c + 3]);
        }
        rIs[t] = (a0 + a1) + (a2 + a3) + b2p[0];
    } else if (t < 192) {
        int j = t - 64, jp = j >> 1;
        const __half2* row = reinterpret_cast<const __half2*>(&S.p1.Hjs[jp][0]);
        float a0 = 0.f, a1 = 0.f, a2 = 0.f, a3 = 0.f;
        if (j & 1) {
#pragma unroll
            for (int c = 0; c < CH; c += 4) {
                a0 += w2hs[c + 0] * __high2float(row[c + 0]);
                a1 += w2hs[c + 1] * __high2float(row[c + 1]);
                a2 += w2hs[c + 2] * __high2float(row[c + 2]);
                a3 += w2hs[c + 3] * __high2float(row[c + 3]);
            }
        } else {
#pragma unroll
            for (int c = 0; c < CH; c += 4) {
                a0 += w2hs[c + 0] * __low2float(row[c + 0]);
                a1 += w2hs[c + 1] * __low2float(row[c + 1]);
                a2 += w2hs[c + 2] * __low2float(row[c + 2]);
                a3 += w2hs[c + 3] * __low2float(row[c + 3]);
            }
        }
        rJn[j] = (a0 + a1) + (a2 + a3);
    }

    int tx = t & 15, ty = t >> 4;   // i = ty+32r; jp = tx+16s
    float accf[2][4][2] = {};

#pragma unroll
    for (int cd = 0; cd < 4; ++cd) {
        __half2 acc[2][4];
#pragma unroll
        for (int r = 0; r < 2; ++r)
#pragma unroll
            for (int s = 0; s < 4; ++s) acc[r][s] = __float2half2_rn(0.f);

#pragma unroll
        for (int c8 = 0; c8 < 8; ++c8) {
            int c = cd * 16 + c8 * 2;
            uint2 wv = *reinterpret_cast<const uint2*>(&wdup[c]);
            __half2 wA = u2h(wv.x), wB = u2h(wv.y);
            uint2 yi[2], zj[4];
#pragma unroll
            for (int r = 0; r < 2; ++r)
                yi[r] = *reinterpret_cast<const uint2*>(&S.p1.His[ty + 32 * r][c]);
#pragma unroll
            for (int s = 0; s < 4; ++s)
                zj[s] = *reinterpret_cast<const uint2*>(&S.p1.Hjs[tx + 16 * s][c]);
#pragma unroll
            for (int r = 0; r < 2; ++r)
#pragma unroll
                for (int s = 0; s < 4; ++s) {
                    __half2 dA = __habs2(__hadd2(u2h(yi[r].x), u2h(zj[s].x)));
                    acc[r][s] = __hfma2(wA, dA, acc[r][s]);
                    __half2 dB = __habs2(__hadd2(u2h(yi[r].y), u2h(zj[s].y)));
                    acc[r][s] = __hfma2(wB, dB, acc[r][s]);
                }
        }
#pragma unroll
        for (int r = 0; r < 2; ++r)
#pragma unroll
            for (int s = 0; s < 4; ++s) {
                float2 f = __half22float2(acc[r][s]);
                accf[r][s][0] += f.x;
                accf[r][s][1] += f.y;
            }
    }

    __syncthreads();   // rIs/rJn final

    // exp (no max subtraction; scores bounded) + block-partial row sums
    float prow[2];
#pragma unroll
    for (int r = 0; r < 2; ++r) {
        float ri = rIs[ty + 32 * r];
        float p = 0.f;
#pragma unroll
        for (int s = 0; s < 4; ++s) {
            int j0 = 2 * (tx + 16 * s);
            float e0 = __expf(ri + rJn[j0]     + accf[r][s][0]);
            float e1 = __expf(ri + rJn[j0 + 1] + accf[r][s][1]);
            accf[r][s][0] = e0;
            accf[r][s][1] = e1;
            p += e0 + e1;
        }
#pragma unroll
        for (int off = 8; off; off >>= 1)
            p += __shfl_xor_sync(0xffffffffu, p, off);
        prow[r] = p;
    }
    if (tx == 0) {
#pragma unroll
        for (int r = 0; r < 2; ++r)
            atomicAdd(&g_rowsum[b * NSEQ + it * 64 + ty + 32 * r], prow[r]);
    }

    // rendezvous: wait for all 8 jt-blocks of this (b, it) — monotonic tickets
    __syncthreads();
    if (t == 0) {
        __threadfence();
        unsigned idx = b * 16 + it;
        unsigned ticket = atomicAdd(&g_cnt[idx], 1u);
        unsigned target = (ticket / 8u + 1u) * 8u;
        while (atomicAdd(&g_cnt[idx], 0u) < target) { __nanosleep(32); }
    }
    __syncthreads();

    if (t < 64) {
        volatile const float* vs = g_rowsum;
        rsum[t] = 1.0f / vs[b * NSEQ + it * 64 + t];
    }
    __syncthreads();

#pragma unroll
    for (int r = 0; r < 2; ++r) {
        int il = ty + 32 * r;
        float inv = rsum[il];
        float* orow = out + ((size_t)(b * NSEQ + it * 64 + il)) * NSEQ + jt * 128;
#pragma unroll
        for (int s = 0; s < 4; ++s) {
            int j0 = 2 * (tx + 16 * s);
            float2 v;
            v.x = accf[r][s][0] * inv;
            v.y = accf[r][s][1] * inv;
            *reinterpret_cast<float2*>(&orow[j0]) = v;
        }
    }
}

// ---------------------------------------------------------------------------
extern "C" void kernel_launch(void* const* d_in, const int* in_sizes, int n_in,
                              void* d_out, int out_size) {
    const float* x  = (const float*)d_in[0];  // [2,1024,64]
    const float* w1 = (const float*)d_in[1];  // [64,64]
    const float* b1 = (const float*)d_in[2];  // [64]
    const float* w2 = (const float*)d_in[3];  // [64]
    const float* b2 = (const float*)d_in[4];  // scalar
    float* out = (float*)d_out;               // [2,1024,1024]

    dim3 g(8, 16, 2);
    k_fused<<<g, 512>>>(x, w1, b1, w2, b2, out);
}

// round 17
// speedup vs baseline: 1.0937x; 1.0937x over previous
#include <cuda_runtime.h>
#include <cuda_fp16.h>

#define NSEQ 1024
#define CH   64
#define NPTS (2 * NSEQ)

// Scratch (allocation-free rule: __device__ globals). fp16 projections.
__device__ __align__(16) __half g_Hi[NPTS * CH];  //  y + b1   (i side)
__device__ __align__(16) __half g_Hj[NPTS * CH];  // -y        (j side, pre-negated)
__device__ float g_rowsum[NPTS];                  // per-(b,i) sum of exp(s)
__device__ unsigned g_cnt[32];                    // per-(b,it) tickets (monotonic)

static __device__ __forceinline__ __half2 u2h(unsigned u) {
    return *reinterpret_cast<const __half2*>(&u);
}
static __device__ __forceinline__ unsigned h2u(__half2 h) {
    return *reinterpret_cast<const unsigned*>(&h);
}

// ---------------------------------------------------------------------------
// K1: y[p][o] = sum_c W1[o][c] * x[p][c];  Hi = half(y+b1); Hj = half(-y)
// 128 blocks x 16 points, 256 threads (proven champion shape).
// Also zeroes g_rowsum for this call (graph-replay determinism).
// ---------------------------------------------------------------------------
__global__ void k1_proj(const float* __restrict__ x,
                        const float* __restrict__ w1,
                        const float* __restrict__ b1) {
    __shared__ float W1T[CH][65];                  // [c][o]
    __shared__ __align__(16) float xsT[CH][20];    // [c][p]
    __shared__ float b1s[CH];

    int t = threadIdx.x;
    int p0 = blockIdx.x * 16;

    // zero reduction scratch (blocks 0-7 cover 2048 floats)
    if (blockIdx.x < 8) g_rowsum[blockIdx.x * 256 + t] = 0.f;

#pragma unroll
    for (int q = t; q < 1024; q += 256) {
        int o = q >> 4, c4 = (q & 15) * 4;
        float4 v = reinterpret_cast<const float4*>(w1)[q];
        W1T[c4 + 0][o] = v.x;
        W1T[c4 + 1][o] = v.y;
        W1T[c4 + 2][o] = v.z;
        W1T[c4 + 3][o] = v.w;
    }
    {
        int pl = t >> 4, c4 = (t & 15) * 4;
        float4 v = reinterpret_cast<const float4*>(x + p0 * CH)[t];
        xsT[c4 + 0][pl] = v.x;
        xsT[c4 + 1][pl] = v.y;
        xsT[c4 + 2][pl] = v.z;
        xsT[c4 + 3][pl] = v.w;
    }
    if (t < CH) b1s[t] = b1[t];
    __syncthreads();

    int o = t & 63, pg = t >> 6;
    float a0 = 0.f, a1 = 0.f, a2 = 0.f, a3 = 0.f;
#pragma unroll
    for (int c = 0; c < CH; ++c) {
        float wv = W1T[c][o];
        float4 xv = *reinterpret_cast<const float4*>(&xsT[c][pg * 4]);
        a0 += wv * xv.x;
        a1 += wv * xv.y;
        a2 += wv * xv.z;
        a3 += wv * xv.w;
    }

    float b1v = b1s[o];
    int pbase = p0 + pg * 4;
    g_Hj[(pbase + 0) * CH + o] = __float2half_rn(-a0);
    g_Hi[(pbase + 0) * CH + o] = __float2half_rn(a0 + b1v);
    g_Hj[(pbase + 1) * CH + o] = __float2half_rn(-a1);
    g_Hi[(pbase + 1) * CH + o] = __float2half_rn(a1 + b1v);
    g_Hj[(pbase + 2) * CH + o] = __float2half_rn(-a2);
    g_Hi[(pbase + 2) * CH + o] = __float2half_rn(a2 + b1v);
    g_Hj[(pbase + 3) * CH + o] = __float2half_rn(-a3);
    g_Hi[(pbase + 3) * CH + o] = __float2half_rn(a3 + b1v);
}

// ---------------------------------------------------------------------------
// K2: scores + fused softmax, one output write. (R12 champion body + PDL.)
// Tile 64 i x 128 j, 256 threads, microtile 4i x 4jp. exp without max
// subtraction (scores bounded); cross-block row sums via atomics + ticket
// rendezvous (256 blocks, 2/SM, single wave). Grid: (jt=8, it=16, b=2).
// Launched with programmatic stream serialization: blocks start during k1,
// stage w2, then cudaGridDependencySynchronize() before touching g_Hi/g_Hj.
// ---------------------------------------------------------------------------
__global__ void __launch_bounds__(256, 2)
k2_scores(const float* __restrict__ w2,
          const float* __restrict__ b2p,
          float* __restrict__ out) {
    __shared__ __align__(16) unsigned His[64][66];   // dup'd (yi,yi)
    __shared__ __align__(16) unsigned Hjs[64][66];   // paired (yj0,yj1)
    __shared__ __align__(16) unsigned wdup[CH];      // dup'd (w2h,w2h)
    __shared__ float w2hs[CH];
    __shared__ float rIs[64], rJn[128];
    __shared__ float rsum[64];

    int t  = threadIdx.x;
    int jt = blockIdx.x, it = blockIdx.y, b = blockIdx.z;
    size_t bb = (size_t)b * NSEQ * CH;

    // --- k1-independent prologue (overlaps with k1 via PDL) ---
    float b2v = 0.f;
    if (t < CH) {
        float wh = 0.5f * w2[t];
        w2hs[t] = wh;
        wdup[t] = h2u(__half2half2(__float2half_rn(wh)));
        b2v = b2p[0];
    }

    // wait for k1's writes to be visible
    cudaGridDependencySynchronize();

    // --- stage His (dup): thread -> row t>>2, 16 channels ---
    {
        int row = t >> 2, c16 = (t & 3) * 16;
        const uint4* src = reinterpret_cast<const uint4*>(
            g_Hi + bb + (size_t)(it * 64 + row) * CH + c16);
        uint4 u0 = src[0], u1 = src[1];
        unsigned wsrc[8] = {u0.x, u0.y, u0.z, u0.w, u1.x, u1.y, u1.z, u1.w};
#pragma unroll
        for (int k = 0; k < 8; ++k) {
            His[row][c16 + 2 * k]     = __byte_perm(wsrc[k], 0, 0x1010);
            His[row][c16 + 2 * k + 1] = __byte_perm(wsrc[k], 0, 0x3232);
        }
    }
    // --- stage Hjs (j-pairs): thread -> jp = t>>2, 16 channels ---
    {
        int jp = t >> 2, c16 = (t & 3) * 16;
        const uint4* pa = reinterpret_cast<const uint4*>(
            g_Hj + bb + (size_t)(jt * 128 + 2 * jp) * CH + c16);
        const uint4* pb = reinterpret_cast<const uint4*>(
            g_Hj + bb + (size_t)(jt * 128 + 2 * jp + 1) * CH + c16);
        uint4 A0 = pa[0], A1 = pa[1];
        uint4 B0 = pb[0], B1 = pb[1];
        unsigned av[8] = {A0.x, A0.y, A0.z, A0.w, A1.x, A1.y, A1.z, A1.w};
        unsigned bv[8] = {B0.x, B0.y, B0.z, B0.w, B1.x, B1.y, B1.z, B1.w};
#pragma unroll
        for (int k = 0; k < 8; ++k) {
            Hjs[jp][c16 + 2 * k]     = __byte_perm(av[k], bv[k], 0x5410);
            Hjs[jp][c16 + 2 * k + 1] = __byte_perm(av[k], bv[k], 0x7632);
        }
    }
    __syncthreads();

    // --- per-row scalars (fp32, ILP-4), overlapped with the main loop ---
    if (t < 64) {
        const __half2* row = reinterpret_cast<const __half2*>(&His[t][0]);
        float a0 = 0.f, a1 = 0.f, a2 = 0.f, a3 = 0.f;
#pragma unroll
        for (int c = 0; c < CH; c += 4) {
            a0 += w2hs[c + 0] * __low2float(row[c + 0]);
            a1 += w2hs[c + 1] * __low2float(row[c + 1]);
            a2 += w2hs[c + 2] * __low2float(row[c + 2]);
            a3 += w2hs[c + 3] * __low2float(row[c + 3]);
        }
        rIs[t] = (a0 + a1) + (a2 + a3) + b2v;
    } else if (t < 192) {
        int j = t - 64, jp = j >> 1;
        const __half2* row = reinterpret_cast<const __half2*>(&Hjs[jp][0]);
        float a0 = 0.f, a1 = 0.f, a2 = 0.f, a3 = 0.f;
        if (j & 1) {
#pragma unroll
            for (int c = 0; c < CH; c += 4) {
                a0 += w2hs[c + 0] * __high2float(row[c + 0]);
                a1 += w2hs[c + 1] * __high2float(row[c + 1]);
                a2 += w2hs[c + 2] * __high2float(row[c + 2]);
                a3 += w2hs[c + 3] * __high2float(row[c + 3]);
            }
        } else {
#pragma unroll
            for (int c = 0; c < CH; c += 4) {
                a0 += w2hs[c + 0] * __low2float(row[c + 0]);
                a1 += w2hs[c + 1] * __low2float(row[c + 1]);
                a2 += w2hs[c + 2] * __low2float(row[c + 2]);
                a3 += w2hs[c + 3] * __low2float(row[c + 3]);
            }
        }
        rJn[j] = (a0 + a1) + (a2 + a3);
    }

    int tx = t & 15, ty = t >> 4;   // i = ty+16r; jp = tx+16s (j = 2jp, 2jp+1)
    float accf[4][4][2] = {};

#pragma unroll
    for (int cd = 0; cd < 4; ++cd) {
        __half2 acc[4][4];
#pragma unroll
        for (int r = 0; r < 4; ++r)
#pragma unroll
            for (int s = 0; s < 4; ++s) acc[r][s] = __float2half2_rn(0.f);

#pragma unroll
        for (int c8 = 0; c8 < 8; ++c8) {
            int c = cd * 16 + c8 * 2;
            uint2 wv = *reinterpret_cast<const uint2*>(&wdup[c]);
            __half2 wA = u2h(wv.x), wB = u2h(wv.y);
            uint2 yi[4], zj[4];
#pragma unroll
            for (int r = 0; r < 4; ++r)
                yi[r] = *reinterpret_cast<const uint2*>(&His[ty + 16 * r][c]);
#pragma unroll
            for (int s = 0; s < 4; ++s)
                zj[s] = *reinterpret_cast<const uint2*>(&Hjs[tx + 16 * s][c]);
#pragma unroll
            for (int r = 0; r < 4; ++r)
#pragma unroll
                for (int s = 0; s < 4; ++s) {
                    __half2 dA = __habs2(__hadd2(u2h(yi[r].x), u2h(zj[s].x)));
                    acc[r][s] = __hfma2(wA, dA, acc[r][s]);
                    __half2 dB = __habs2(__hadd2(u2h(yi[r].y), u2h(zj[s].y)));
                    acc[r][s] = __hfma2(wB, dB, acc[r][s]);
                }
        }
#pragma unroll
        for (int r = 0; r < 4; ++r)
#pragma unroll
            for (int s = 0; s < 4; ++s) {
                float2 f = __half22float2(acc[r][s]);
                accf[r][s][0] += f.x;
                accf[r][s][1] += f.y;
            }
    }

    __syncthreads();   // rIs/rJn final

    // --- exp (no max subtraction; scores bounded) + block-partial row sums ---
    float prow[4];
#pragma unroll
    for (int r = 0; r < 4; ++r) {
        float ri = rIs[ty + 16 * r];
        float p = 0.f;
#pragma unroll
        for (int s = 0; s < 4; ++s) {
            int j0 = 2 * (tx + 16 * s);
            float e0 = __expf(ri + rJn[j0]     + accf[r][s][0]);
            float e1 = __expf(ri + rJn[j0 + 1] + accf[r][s][1]);
            accf[r][s][0] = e0;
            accf[r][s][1] = e1;
            p += e0 + e1;
        }
#pragma unroll
        for (int off = 8; off; off >>= 1)
            p += __shfl_xor_sync(0xffffffffu, p, off);
        prow[r] = p;
    }
    if (tx == 0) {
#pragma unroll
        for (int r = 0; r < 4; ++r)
            atomicAdd(&g_rowsum[b * NSEQ + it * 64 + ty + 16 * r], prow[r]);
    }

    // --- rendezvous: all 8 jt-blocks of this (b, it) — monotonic tickets ---
    __syncthreads();
    if (t == 0) {
        __threadfence();
        unsigned idx = b * 16 + it;
        unsigned ticket = atomicAdd(&g_cnt[idx], 1u);
        unsigned target = (ticket / 8u + 1u) * 8u;
        while (atomicAdd(&g_cnt[idx], 0u) < target) { __nanosleep(32); }
    }
    __syncthreads();

    if (t < 64) {
        volatile const float* vs = g_rowsum;
        rsum[t] = 1.0f / vs[b * NSEQ + it * 64 + t];
    }
    __syncthreads();

#pragma unroll
    for (int r = 0; r < 4; ++r) {
        int il = ty + 16 * r;
        float inv = rsum[il];
        float* orow = out + ((size_t)(b * NSEQ + it * 64 + il)) * NSEQ + jt * 128;
#pragma unroll
        for (int s = 0; s < 4; ++s) {
            int j0 = 2 * (tx + 16 * s);
            float2 v;
            v.x = accf[r][s][0] * inv;
            v.y = accf[r][s][1] * inv;
            *reinterpret_cast<float2*>(&orow[j0]) = v;
        }
    }
}

// ---------------------------------------------------------------------------
extern "C" void kernel_launch(void* const* d_in, const int* in_sizes, int n_in,
                              void* d_out, int out_size) {
    const float* x  = (const float*)d_in[0];  // [2,1024,64]
    const float* w1 = (const float*)d_in[1];  // [64,64]
    const float* b1 = (const float*)d_in[2];  // [64]
    const float* w2 = (const float*)d_in[3];  // [64]
    const float* b2 = (const float*)d_in[4];  // scalar
    float* out = (float*)d_out;               // [2,1024,1024]

    k1_proj<<<128, 256>>>(x, w1, b1);

    // k2 with programmatic dependent launch: overlaps launch + prologue with k1
    cudaLaunchConfig_t cfg = {};
    cfg.gridDim  = dim3(8, 16, 2);
    cfg.blockDim = dim3(256, 1, 1);
    cudaLaunchAttribute attrs[1];
    attrs[0].id = cudaLaunchAttributeProgrammaticStreamSerialization;
    attrs[0].val.programmaticStreamSerializationAllowed = 1;
    cfg.attrs = attrs;
    cfg.numAttrs = 1;
    cudaLaunchKernelEx(&cfg, k2_scores, w2, b2, (float*)d_out);
}